// round 10
// baseline (speedup 1.0000x reference)
#include <cuda_runtime.h>
#include <cstdint>

#define HD 128
#define WD 128
#define OC 128
#define CIN 64
#define XSW 72                  // half-tile x row stride (floats): 72 % 32 == 8 -> conflict-free
#define WBYTES 32768            // one tap of pre-arranged B fragments (full N=128)

// smem byte offsets (per-CTA dynamic smem = 108.7 KB -> 2 CTAs/SM)
#define SM_XS   0               // 4 * 64 * 72 * 4 = 73728
#define SM_W    73728           // 32768 (single buffer)
#define SM_CS   106496          // 4 * 72 * 4 = 1152
#define SM_PS   107648          // 2 * 64 * 4 = 512
#define SM_BIAS 108160          // 512
#define SM_MB   108672          // wb, cb
#define SM_TOT  108704

// B fragments, register-image order: [tap][s(8)][g(16)][lane(32)][2]
__device__ __align__(128) float g_Wf[9 * 8 * 16 * 32 * 2];

// ---------- helpers ----------
__device__ __forceinline__ uint32_t smem_u32(const void* p) {
    uint32_t a;
    asm("{ .reg .u64 t; cvta.to.shared.u64 t, %1; cvt.u32.u64 %0, t; }" : "=r"(a) : "l"(p));
    return a;
}
__device__ __forceinline__ float tf32r(float v) {
    float r; asm("cvt.rna.tf32.f32 %0, %1;" : "=f"(r) : "f"(v)); return r;
}
#define MB_INIT(mb, c)   asm volatile("mbarrier.init.shared.b64 [%0], %1;" :: "r"(mb), "r"((uint32_t)(c)) : "memory")
#define MB_EXPECT(mb, n) asm volatile("mbarrier.arrive.expect_tx.shared.b64 _, [%0], %1;" :: "r"(mb), "r"((uint32_t)(n)) : "memory")
#define MB_ARRIVE(mb)    asm volatile("mbarrier.arrive.release.cta.shared::cta.b64 _, [%0];" :: "r"(mb) : "memory")
#define BULK_G2S(dst, src, n, mb) \
    asm volatile("cp.async.bulk.shared::cta.global.mbarrier::complete_tx::bytes [%0], [%1], %2, [%3];" \
                 :: "r"(dst), "l"(src), "r"((uint32_t)(n)), "r"(mb) : "memory")
#define MB_WAIT(mb, par) do {                                                          \
    uint32_t _m = (mb), _p = (par), _d;                                                \
    asm volatile("{\n\t.reg .pred p;\n\t"                                              \
        "mbarrier.try_wait.parity.acquire.cta.shared::cta.b64 p, [%1], %2;\n\t"        \
        "selp.b32 %0,1,0,p;\n\t}" : "=r"(_d) : "r"(_m), "r"(_p) : "memory");           \
    if (!_d) {                                                                         \
        asm volatile("{\n\t.reg .pred P1;\n\tWL_%=:\n\t"                               \
            "mbarrier.try_wait.parity.acquire.cta.shared::cta.b64 P1, [%0], %1, 0x989680;\n\t" \
            "@P1 bra.uni WDN_%=;\n\tbra.uni WL_%=;\n\tWDN_%=:\n\t}"                    \
            :: "r"(_m), "r"(_p) : "memory");                                           \
    }                                                                                  \
} while (0)

// m16n8k8 tf32 HMMA (sm_80+ baseline ISA)
#define MMA8(d, a, bq)                                                                 \
    asm volatile("mma.sync.aligned.m16n8k8.row.col.f32.tf32.tf32.f32 "                 \
        "{%0,%1,%2,%3}, {%4,%5,%6,%7}, {%8,%9}, {%0,%1,%2,%3};"                        \
        : "+f"((d)[0]), "+f"((d)[1]), "+f"((d)[2]), "+f"((d)[3])                       \
        : "r"(__float_as_uint((a)[0])), "r"(__float_as_uint((a)[1])),                  \
          "r"(__float_as_uint((a)[2])), "r"(__float_as_uint((a)[3])),                  \
          "r"(__float_as_uint((bq).x)), "r"(__float_as_uint((bq).y)))

// load frags for step ss into slot sl (4 m-frags, 8 n-frags)
#define LOAD_FRAGS(sl, Abase, Bbase, ss) do {                                          \
    const float*  _Ap = (Abase) + (ss) * 8 * XSW;                                      \
    const float2* _Bp = (Bbase) + (ss) * 512;                                          \
    _Pragma("unroll") for (int _ni = 0; _ni < 8; _ni++) bq[sl][_ni] = _Bp[_ni * 32];   \
    _Pragma("unroll") for (int _mi = 0; _mi < 4; _mi++) {                              \
        a[sl][_mi][0] = _Ap[_mi * 16];                                                 \
        a[sl][_mi][1] = _Ap[_mi * 16 + 8];                                             \
        a[sl][_mi][2] = _Ap[_mi * 16 + 4 * XSW];                                       \
        a[sl][_mi][3] = _Ap[_mi * 16 + 8 + 4 * XSW];                                   \
    }                                                                                  \
} while (0)

// ---------- prepass: weights -> per-thread B fragment images ----------
__global__ void prep_w(const float* __restrict__ wt) {
    int i = blockIdx.x * blockDim.x + threadIdx.x;   // one float2 per thread
    if (i >= 9 * 8 * 16 * 32) return;
    int tap = i >> 12;
    int r = i & 4095;
    int s = r >> 9;
    int g = (r >> 5) & 15;
    int lane = r & 31;
    int o = g * 8 + (lane >> 2);
    int k0 = s * 8 + (lane & 3);
    float2 v;
    v.x = tf32r(wt[o * 576 + k0 * 9 + tap]);          // wt[o][ci][kh][kw], tap = kh*3+kw
    v.y = tf32r(wt[o * 576 + (k0 + 4) * 9 + tap]);
    ((float2*)g_Wf)[i] = v;
}

// ---------- main kernel: one CTA per (b, h-pair, w-half), 128 threads / 4 warps ----------
__global__ __launch_bounds__(128, 2)
void patchconv_mma(const float* __restrict__ x, const float* __restrict__ bias,
                   float* __restrict__ out) {
    extern __shared__ __align__(16) char smem[];
    float* sxs   = (float*)(smem + SM_XS);    // [r(4)][ci(64)][j(72)], j = xcol - wh*64 + 1
    float* scs   = (float*)(smem + SM_CS);    // channel sums [r][j]
    float* sps   = (float*)(smem + SM_PS);    // 3x3 patch sums [hl][w0r]
    float* sbias = (float*)(smem + SM_BIAS);
    const uint32_t sb = smem_u32(smem);
    const uint32_t wb = sb + SM_MB, cb = sb + SM_MB + 8;

    const int tid = threadIdx.x, lane = tid & 31, wid = tid >> 5;
    const int h0 = blockIdx.x * 2, wh = blockIdx.y, b = blockIdx.z;
    const int wbase = wh * 64;

    if (tid == 0) { MB_INIT(wb, 1); MB_INIT(cb, 4); }
    sbias[tid] = bias[tid];
    __syncthreads();
    if (tid == 0) { MB_EXPECT(wb, WBYTES); BULK_G2S(sb + SM_W, (const void*)g_Wf, WBYTES, wb); }

    // ---- stage x: 4 halo rows, columns wbase-1 .. wbase+66, tf32-rounded ----
    const float* xb = x + (size_t)b * CIN * HD * WD;
    for (int idx = wid; idx < 4 * 64; idx += 4) {
        int r = idx >> 6, ci = idx & 63;
        int hr = h0 - 1 + r;
        bool rok = (unsigned)hr < 128u;
        const float* src = xb + ((size_t)ci * HD + hr) * WD;
        float* dst = sxs + (r * 64 + ci) * XSW;
        #pragma unroll
        for (int jj = 0; jj < 3; jj++) {
            int j = lane + jj * 32;
            if (j < 68) {
                int g = wbase + j - 1;
                float v = (rok && (unsigned)g < 128u) ? tf32r(__ldg(src + g)) : 0.f;
                dst[j] = v;
            }
        }
    }
    __syncthreads();

    // ---- channel sums + 3x3 patch sums (rank-1 term) ----
    for (int p = tid; p < 4 * 68; p += 128) {
        int r = p / 68, j = p - r * 68;
        float s = 0.f;
        const float* c = sxs + r * 64 * XSW + j;
        #pragma unroll 8
        for (int k = 0; k < 64; k++) s += c[k * XSW];
        scs[r * XSW + j] = s;
    }
    __syncthreads();
    {
        int hl = tid >> 6, wo = tid & 63;
        float s = 0.f;
        #pragma unroll
        for (int kh = 0; kh < 3; kh++)
            #pragma unroll
            for (int kw = 0; kw < 3; kw++)
                s += scs[(hl + kh) * XSW + wo + kw];
        sps[tid] = s;
    }
    __syncthreads();

    // ---- main loop: 9 taps, warp tile 64M x 64N (hl x warp_n), single-W-buffer ----
    const int hl = wid >> 1, warp_n = wid & 1;

    float acc[4][8][4];
    #pragma unroll
    for (int mi = 0; mi < 4; mi++)
        #pragma unroll
        for (int ni = 0; ni < 8; ni++)
            #pragma unroll
            for (int j = 0; j < 4; j++) acc[mi][ni][j] = 0.f;

    float a[2][4][4];
    float2 bq[2][8];
    const float2* Bb = (const float2*)(smem + SM_W) + warp_n * 256 + lane;

    // prologue: wait tap-0 weights (copy_0, parity 0), load step-0 frags into slot 0
    MB_WAIT(wb, 0);
    {
        const float* Ab0 = sxs + hl * 64 * XSW + (lane & 3) * XSW + (lane >> 2);
        LOAD_FRAGS(0, Ab0, Bb, 0);
    }

    #pragma unroll 1
    for (int t = 0; t < 9; t++) {
        const int kh = t / 3, kw = t - kh * 3;
        const float* Ab = sxs + (hl + kh) * 64 * XSW + (lane & 3) * XSW + kw + (lane >> 2);

        #pragma unroll
        for (int s = 0; s < 8; s++) {
            const int cur = s & 1, nxt = cur ^ 1;
            if (s < 6) {
                LOAD_FRAGS(nxt, Ab, Bb, s + 1);
            } else if (s == 6) {
                LOAD_FRAGS(nxt, Ab, Bb, 7);       // last smem-B read of tap t
                if (lane == 0) MB_ARRIVE(cb);
                if (tid == 0) {
                    MB_WAIT(cb, t & 1);           // all 4 warps done with buffer
                    if (t < 8) {
                        MB_EXPECT(wb, WBYTES);
                        BULK_G2S(sb + SM_W, (const void*)(g_Wf + (t + 1) * 8192), WBYTES, wb);
                    }
                }
            } else {                               // s == 7
                if (t < 8) {
                    MB_WAIT(wb, (t + 1) & 1);     // tap t+1 weights landed
                    const int nt = t + 1, nkh = nt / 3, nkw = nt - nkh * 3;
                    const float* An = sxs + (hl + nkh) * 64 * XSW + (lane & 3) * XSW + nkw + (lane >> 2);
                    LOAD_FRAGS(nxt, An, Bb, 0);
                }
            }
            #pragma unroll
            for (int mi = 0; mi < 4; mi++)
                #pragma unroll
                for (int ni = 0; ni < 8; ni++)
                    MMA8(acc[mi][ni], a[cur][mi], bq[cur][ni]);
        }
    }

    // ---- epilogue: + bias[o] + 0.1*(h+w)*patch_sum, 32B-sector-aligned stores ----
    const int hg = h0 + hl;
    const int ob = warp_n * 64;
    float* outb = out + (size_t)b * OC * HD * WD + (size_t)hg * WD + wbase;
    #pragma unroll
    for (int mi = 0; mi < 4; mi++) {
        int w0r = mi * 16 + (lane >> 2);
        float c0 = 0.1f * (float)(hg + wbase + w0r) * sps[hl * 64 + w0r];
        float c1 = 0.1f * (float)(hg + wbase + w0r + 8) * sps[hl * 64 + w0r + 8];
        #pragma unroll
        for (int ni = 0; ni < 8; ni++) {
            int o = ob + ni * 8 + (lane & 3) * 2;
            float bz0 = sbias[o], bz1 = sbias[o + 1];
            float* p0 = outb + (size_t)o * (HD * WD);
            float* p1 = p0 + HD * WD;
            p0[w0r]     = acc[mi][ni][0] + c0 + bz0;
            p1[w0r]     = acc[mi][ni][1] + c0 + bz1;
            p0[w0r + 8] = acc[mi][ni][2] + c1 + bz0;
            p1[w0r + 8] = acc[mi][ni][3] + c1 + bz1;
        }
    }
}

extern "C" void kernel_launch(void* const* d_in, const int* in_sizes, int n_in,
                              void* d_out, int out_size) {
    const float* x    = (const float*)d_in[0];
    const float* wt   = (const float*)d_in[1];
    const float* bias = (const float*)d_in[2];
    float* out        = (float*)d_out;
    cudaFuncSetAttribute(patchconv_mma, cudaFuncAttributeMaxDynamicSharedMemorySize, SM_TOT);
    prep_w<<<(9 * 8 * 16 * 32 + 255) / 256, 256>>>(wt);
    patchconv_mma<<<dim3(64, 2, 16), 128, SM_TOT>>>(x, bias, out);
}

// round 11
// speedup vs baseline: 1.7730x; 1.7730x over previous
#include <cuda_runtime.h>
#include <cstdint>

#define HD 128
#define WD 128
#define OC 128
#define CIN 64
#define XST 136                 // x smem row stride (floats): conflict-free frag reads
#define WBYTES 32768            // one tap of pre-arranged B fragments

// smem byte offsets
#define SM_XS   0               // 4 * 64 * 136 * 4 = 139264
#define SM_W    139264          // 2 * 32768 = 65536
#define SM_CS   204800          // 4 * 136 * 4 = 2176
#define SM_PS   206976          // 2 * 128 * 4 = 1024
#define SM_BIAS 208000          // 512
#define SM_MB   208512          // wb0, wb1, cb0, cb1
#define SM_TOT  208560

// B fragments, register-image order: [tap][s(8)][g(16)][lane(32)][2]
__device__ __align__(128) float g_Wf[9 * 8 * 16 * 32 * 2];

// ---------- helpers ----------
__device__ __forceinline__ uint32_t smem_u32(const void* p) {
    uint32_t a;
    asm("{ .reg .u64 t; cvta.to.shared.u64 t, %1; cvt.u32.u64 %0, t; }" : "=r"(a) : "l"(p));
    return a;
}
__device__ __forceinline__ float tf32r(float v) {
    float r; asm("cvt.rna.tf32.f32 %0, %1;" : "=f"(r) : "f"(v)); return r;
}
#define MB_INIT(mb, c)   asm volatile("mbarrier.init.shared.b64 [%0], %1;" :: "r"(mb), "r"((uint32_t)(c)) : "memory")
#define MB_EXPECT(mb, n) asm volatile("mbarrier.arrive.expect_tx.shared.b64 _, [%0], %1;" :: "r"(mb), "r"((uint32_t)(n)) : "memory")
#define MB_ARRIVE(mb)    asm volatile("mbarrier.arrive.shared.b64 _, [%0];" :: "r"(mb) : "memory")
#define BULK_G2S(dst, src, n, mb) \
    asm volatile("cp.async.bulk.shared::cta.global.mbarrier::complete_tx::bytes [%0], [%1], %2, [%3];" \
                 :: "r"(dst), "l"(src), "r"((uint32_t)(n)), "r"(mb) : "memory")
#define MB_WAIT(mb, par) do {                                                          \
    uint32_t _m = (mb), _p = (par), _d;                                                \
    asm volatile("{\n\t.reg .pred p;\n\t"                                              \
        "mbarrier.try_wait.parity.acquire.cta.shared::cta.b64 p, [%1], %2;\n\t"        \
        "selp.b32 %0,1,0,p;\n\t}" : "=r"(_d) : "r"(_m), "r"(_p) : "memory");           \
    if (!_d) {                                                                         \
        asm volatile("{\n\t.reg .pred P1;\n\tWL_%=:\n\t"                               \
            "mbarrier.try_wait.parity.acquire.cta.shared::cta.b64 P1, [%0], %1, 0x989680;\n\t" \
            "@P1 bra.uni WDN_%=;\n\tbra.uni WL_%=;\n\tWDN_%=:\n\t}"                    \
            :: "r"(_m), "r"(_p) : "memory");                                           \
    }                                                                                  \
} while (0)

// cp.async 16B with zero-fill (src_size = 0 or 16)
#define CP_ASYNC16(dst, src, sz) \
    asm volatile("cp.async.ca.shared.global [%0], [%1], 16, %2;" \
                 :: "r"((uint32_t)(dst)), "l"(src), "r"((uint32_t)(sz)) : "memory")
#define CP_COMMIT()  asm volatile("cp.async.commit_group;" ::: "memory")
#define CP_WAIT0()   asm volatile("cp.async.wait_group 0;" ::: "memory")

// m16n8k8 tf32 HMMA (sm_80+ baseline ISA)
#define MMA8(d, a, bq)                                                                 \
    asm volatile("mma.sync.aligned.m16n8k8.row.col.f32.tf32.tf32.f32 "                 \
        "{%0,%1,%2,%3}, {%4,%5,%6,%7}, {%8,%9}, {%0,%1,%2,%3};"                        \
        : "+f"((d)[0]), "+f"((d)[1]), "+f"((d)[2]), "+f"((d)[3])                       \
        : "r"(__float_as_uint((a)[0])), "r"(__float_as_uint((a)[1])),                  \
          "r"(__float_as_uint((a)[2])), "r"(__float_as_uint((a)[3])),                  \
          "r"(__float_as_uint((bq).x)), "r"(__float_as_uint((bq).y)))

#define LOAD_A(sl, Abase, ss) do {                                                     \
    const float* _Ap = (Abase) + (ss) * 8 * XST;                                       \
    _Pragma("unroll") for (int _mi = 0; _mi < 4; _mi++) {                              \
        a[sl][_mi][0] = _Ap[_mi * 16];                                                 \
        a[sl][_mi][1] = _Ap[_mi * 16 + 8];                                             \
        a[sl][_mi][2] = _Ap[_mi * 16 + 4 * XST];                                       \
        a[sl][_mi][3] = _Ap[_mi * 16 + 8 + 4 * XST];                                   \
    }                                                                                  \
} while (0)
#define LOAD_B(sl, Bbase, ss) do {                                                     \
    const float2* _Bp = (Bbase) + (ss) * 512;                                          \
    _Pragma("unroll") for (int _ni = 0; _ni < 8; _ni++) bq[sl][_ni] = _Bp[_ni * 32];   \
} while (0)
#define LOAD_FRAGS(sl, Abase, Bbase, ss) do { LOAD_B(sl, Bbase, ss); LOAD_A(sl, Abase, ss); } while (0)

// ---------- prepass: weights -> per-thread B fragment images ----------
__global__ void prep_w(const float* __restrict__ wt) {
    int i = blockIdx.x * blockDim.x + threadIdx.x;   // one float2 per thread
    if (i >= 9 * 8 * 16 * 32) return;
    int tap = i >> 12;
    int r = i & 4095;
    int s = r >> 9;
    int g = (r >> 5) & 15;
    int lane = r & 31;
    int o = g * 8 + (lane >> 2);
    int k0 = s * 8 + (lane & 3);
    float2 v;
    v.x = tf32r(wt[o * 576 + k0 * 9 + tap]);          // wt[o][ci][kh][kw], tap = kh*3+kw
    v.y = tf32r(wt[o * 576 + (k0 + 4) * 9 + tap]);
    ((float2*)g_Wf)[i] = v;
}

// ---------- main kernel: one CTA per (b, h-pair), 256 threads / 8 warps ----------
__global__ __launch_bounds__(256, 1)
void patchconv_mma(const float* __restrict__ x, const float* __restrict__ bias,
                   float* __restrict__ out) {
    extern __shared__ __align__(16) char smem[];
    float* sxs   = (float*)(smem + SM_XS);    // [r(4)][ci(64)][w(136)], w idx = xcol+4
    float* scs   = (float*)(smem + SM_CS);    // channel sums [r][w]
    float* sps   = (float*)(smem + SM_PS);    // 3x3 patch sums [hl][w]
    float* sbias = (float*)(smem + SM_BIAS);
    const uint32_t sb  = smem_u32(smem);
    const uint32_t wb0 = sb + SM_MB,      wb1 = sb + SM_MB + 8;
    const uint32_t cb0 = sb + SM_MB + 16, cb1 = sb + SM_MB + 24;

    const int tid = threadIdx.x, lane = tid & 31, wid = tid >> 5;
    const int h0 = blockIdx.x * 2, b = blockIdx.y;

    if (tid == 0) { MB_INIT(wb0, 1); MB_INIT(wb1, 1); MB_INIT(cb0, 8); MB_INIT(cb1, 8); }
    if (tid < 128) sbias[tid] = bias[tid];
    __syncthreads();
    if (tid == 0) { MB_EXPECT(wb0, WBYTES); BULK_G2S(sb + SM_W, (const void*)g_Wf, WBYTES, wb0); }

    const float* xb = x + (size_t)b * CIN * HD * WD;

    // ---- rows 2,3 (hr = h0+1, h0+2): cp.async raw copy, rounded later in-smem ----
    // chunk id -> (rr, ci, c): 34 16B-chunks per row; c==0 and c==33 are zero halo.
    #pragma unroll
    for (int it = 0; it < 17; it++) {
        int id = tid + it * 256;                 // 17*256 = 4352 = 2*64*34
        int c  = id % 34;
        int ci = (id / 34) & 63;
        int rr = id / (34 * 64);                 // 0 -> row2, 1 -> row3
        int hr = h0 + 1 + rr;
        bool ok = (hr < 128) && (c >= 1) && (c <= 32);
        uint32_t dst = sb + SM_XS + (((2 + rr) * 64 + ci) * XST + c * 4) * 4;
        const float* src = ok ? (xb + ((size_t)ci * HD + hr) * WD + (c * 4 - 4)) : xb;
        CP_ASYNC16(dst, src, ok ? 16 : 0);
    }
    CP_COMMIT();

    // ---- rows 0,1 (hr = h0-1, h0): LDG + rna rounding (needed by taps 0-2) ----
    for (int idx = wid; idx < 2 * 64; idx += 8) {
        int r = idx >> 6, ci = idx & 63;
        int hr = h0 - 1 + r;
        float4 v = make_float4(0.f, 0.f, 0.f, 0.f);
        if ((unsigned)hr < 128u)
            v = *(const float4*)(xb + ((size_t)ci * HD + hr) * WD + lane * 4);
        v.x = tf32r(v.x); v.y = tf32r(v.y); v.z = tf32r(v.z); v.w = tf32r(v.w);
        float* d = sxs + (r * 64 + ci) * XST;
        *(float4*)(d + 4 + lane * 4) = v;
        if (lane < 2) *(float4*)(d + lane * 132) = make_float4(0.f, 0.f, 0.f, 0.f);
    }
    __syncthreads();

    // ---- main loop: 9 taps, warp tile 64M x 64N, no CTA barriers except t==3 ----
    const int warp_m = wid >> 1, warp_n = wid & 1;
    const int hl = warp_m >> 1;
    const int wb = (warp_m & 1) * 64;
    const int ob = warp_n * 64;

    float acc[4][8][4];
    #pragma unroll
    for (int mi = 0; mi < 4; mi++)
        #pragma unroll
        for (int ni = 0; ni < 8; ni++)
            #pragma unroll
            for (int j = 0; j < 4; j++) acc[mi][ni][j] = 0.f;

    float a[2][4][4];
    float2 bq[2][8];

    // prologue: wait tap-0 weights, load step-0 frags into slot 0
    MB_WAIT(wb0, 0);
    {
        const float*  Ab = sxs + hl * 64 * XST + (lane & 3) * XST + wb + 3 + (lane >> 2);
        const float2* Bb = (const float2*)(smem + SM_W) + warp_n * 256 + lane;
        LOAD_FRAGS(0, Ab, Bb, 0);
    }

    #pragma unroll 1
    for (int t = 0; t < 9; t++) {
        const int buf = t & 1;

        if (t == 3) {
            // rows 2,3 DMA done long ago under taps 0-2; round in place, then sums.
            CP_WAIT0();
            __syncthreads();
            #pragma unroll
            for (int it = 0; it < 17; it++) {
                int id = tid + it * 256;
                int c  = id % 34;
                int ci = (id / 34) & 63;
                int rr = id / (34 * 64);
                float4* p = (float4*)(sxs + ((2 + rr) * 64 + ci) * XST + c * 4);
                float4 v = *p;
                v.x = tf32r(v.x); v.y = tf32r(v.y); v.z = tf32r(v.z); v.w = tf32r(v.w);
                *p = v;
            }
            __syncthreads();
            // channel sums + 3x3 patch sums (rank-1 term)
            for (int p = tid; p < 4 * XST; p += 256) {
                int r = p / XST, w = p - r * XST;
                float s = 0.f;
                const float* c = sxs + r * 64 * XST + w;
                #pragma unroll 8
                for (int k = 0; k < 64; k++) s += c[k * XST];
                scs[p] = s;
            }
            __syncthreads();
            {
                int phl = tid >> 7, wo = tid & 127;
                float s = 0.f;
                #pragma unroll
                for (int kh = 0; kh < 3; kh++)
                    #pragma unroll
                    for (int kw = 0; kw < 3; kw++)
                        s += scs[(phl + kh) * XST + wo + kw + 3];
                sps[tid] = s;
            }
            __syncthreads();
            // reload tap-3 step-0 A frags (deferred from t==2 s==7: row 2 was raw then)
            const float* A3 = sxs + (hl + 1) * 64 * XST + (lane & 3) * XST + wb + 3 + (lane >> 2);
            LOAD_A(0, A3, 0);
        }

        // tid0: refill other buffer with tap t+1 weights once all warps consumed it
        if (t < 8 && tid == 0) {
            const uint32_t nbm = buf ? wb0 : wb1;
            const uint32_t ncb = buf ? cb0 : cb1;
            if (t >= 1) MB_WAIT(ncb, ((t - 1) >> 1) & 1);
            MB_EXPECT(nbm, WBYTES);
            BULK_G2S(sb + SM_W + (buf ^ 1) * WBYTES, (const void*)(g_Wf + (t + 1) * 8192), WBYTES, nbm);
        }

        const int kh = t / 3, kw = t - kh * 3;
        const float*  Ab = sxs + (hl + kh) * 64 * XST + (lane & 3) * XST + wb + kw + 3 + (lane >> 2);
        const float2* Bb = (const float2*)(smem + SM_W + buf * WBYTES) + warp_n * 256 + lane;

        #pragma unroll
        for (int s = 0; s < 8; s++) {
            const int cur = s & 1, nxt = cur ^ 1;
            if (s < 7) {
                LOAD_FRAGS(nxt, Ab, Bb, s + 1);
            } else {
                // all B-frag reads of tap t issued -> signal buffer consumed
                if (lane == 0) MB_ARRIVE(buf ? cb1 : cb0);
                if (t < 8) {
                    // prefetch tap t+1 step 0 (after its weights land)
                    MB_WAIT(buf ? wb0 : wb1, ((t + 1) >> 1) & 1);
                    const int nt = t + 1, nkh = nt / 3, nkw = nt - nkh * 3;
                    const float2* Bn = (const float2*)(smem + SM_W + (nt & 1) * WBYTES) + warp_n * 256 + lane;
                    LOAD_B(nxt, Bn, 0);
                    if (t != 2) {   // t==2: row 2 not rounded yet; A deferred to t==3 top
                        const float* An = sxs + (hl + nkh) * 64 * XST + (lane & 3) * XST + wb + nkw + 3 + (lane >> 2);
                        LOAD_A(nxt, An, 0);
                    }
                }
            }
            #pragma unroll
            for (int mi = 0; mi < 4; mi++)
                #pragma unroll
                for (int ni = 0; ni < 8; ni++)
                    MMA8(acc[mi][ni], a[cur][mi], bq[cur][ni]);
        }
    }

    // ---- epilogue: + bias[o] + 0.1*(h+w)*patch_sum, 32B-sector-aligned stores ----
    const int hg = h0 + hl;
    float* outb = out + (size_t)b * OC * HD * WD + (size_t)hg * WD;
    #pragma unroll
    for (int mi = 0; mi < 4; mi++) {
        int w0r = wb + mi * 16 + (lane >> 2);
        float c0 = 0.1f * (float)(hg + w0r) * sps[hl * 128 + w0r];
        float c1 = 0.1f * (float)(hg + w0r + 8) * sps[hl * 128 + w0r + 8];
        #pragma unroll
        for (int ni = 0; ni < 8; ni++) {
            int o = ob + ni * 8 + (lane & 3) * 2;
            float bz0 = sbias[o], bz1 = sbias[o + 1];
            float* p0 = outb + (size_t)o * (HD * WD);
            float* p1 = p0 + HD * WD;
            p0[w0r]     = acc[mi][ni][0] + c0 + bz0;
            p1[w0r]     = acc[mi][ni][1] + c0 + bz1;
            p0[w0r + 8] = acc[mi][ni][2] + c1 + bz0;
            p1[w0r + 8] = acc[mi][ni][3] + c1 + bz1;
        }
    }
}

extern "C" void kernel_launch(void* const* d_in, const int* in_sizes, int n_in,
                              void* d_out, int out_size) {
    const float* x    = (const float*)d_in[0];
    const float* wt   = (const float*)d_in[1];
    const float* bias = (const float*)d_in[2];
    float* out        = (float*)d_out;
    cudaFuncSetAttribute(patchconv_mma, cudaFuncAttributeMaxDynamicSharedMemorySize, SM_TOT);
    prep_w<<<(9 * 8 * 16 * 32 + 255) / 256, 256>>>(wt);
    patchconv_mma<<<dim3(64, 16), 256, SM_TOT>>>(x, bias, out);
}

// round 12
// speedup vs baseline: 1.8052x; 1.0182x over previous
#include <cuda_runtime.h>
#include <cstdint>

#define HD 128
#define WD 128
#define OC 128
#define CIN 64
#define XST 136                 // x smem row stride (floats): conflict-free frag reads
#define WBYTES 32768            // one tap of pre-arranged B fragments

// smem byte offsets
#define SM_XS   0               // 4 * 64 * 136 * 4 = 139264
#define SM_W    139264          // 2 * 32768 = 65536
#define SM_CS   204800          // 4 * 136 * 4 = 2176
#define SM_BIAS 208000          // 512
#define SM_MB   208512          // wb0, wb1, cb0, cb1, rmb, smb
#define SM_TOT  208576

// B fragments, register-image order: [tap][s(8)][g(16)][lane(32)][2]
__device__ __align__(128) float g_Wf[9 * 8 * 16 * 32 * 2];

// ---------- helpers ----------
__device__ __forceinline__ uint32_t smem_u32(const void* p) {
    uint32_t a;
    asm("{ .reg .u64 t; cvta.to.shared.u64 t, %1; cvt.u32.u64 %0, t; }" : "=r"(a) : "l"(p));
    return a;
}
__device__ __forceinline__ float tf32r(float v) {
    float r; asm("cvt.rna.tf32.f32 %0, %1;" : "=f"(r) : "f"(v)); return r;
}
#define MB_INIT(mb, c)   asm volatile("mbarrier.init.shared.b64 [%0], %1;" :: "r"(mb), "r"((uint32_t)(c)) : "memory")
#define MB_EXPECT(mb, n) asm volatile("mbarrier.arrive.expect_tx.shared.b64 _, [%0], %1;" :: "r"(mb), "r"((uint32_t)(n)) : "memory")
#define MB_ARRIVE(mb)    asm volatile("mbarrier.arrive.shared.b64 _, [%0];" :: "r"(mb) : "memory")
#define MB_ARRIVE_REL(mb) asm volatile("mbarrier.arrive.release.cta.shared::cta.b64 _, [%0];" :: "r"(mb) : "memory")
#define BULK_G2S(dst, src, n, mb) \
    asm volatile("cp.async.bulk.shared::cta.global.mbarrier::complete_tx::bytes [%0], [%1], %2, [%3];" \
                 :: "r"(dst), "l"(src), "r"((uint32_t)(n)), "r"(mb) : "memory")
#define MB_WAIT(mb, par) do {                                                          \
    uint32_t _m = (mb), _p = (par), _d;                                                \
    asm volatile("{\n\t.reg .pred p;\n\t"                                              \
        "mbarrier.try_wait.parity.acquire.cta.shared::cta.b64 p, [%1], %2;\n\t"        \
        "selp.b32 %0,1,0,p;\n\t}" : "=r"(_d) : "r"(_m), "r"(_p) : "memory");           \
    if (!_d) {                                                                         \
        asm volatile("{\n\t.reg .pred P1;\n\tWL_%=:\n\t"                               \
            "mbarrier.try_wait.parity.acquire.cta.shared::cta.b64 P1, [%0], %1, 0x989680;\n\t" \
            "@P1 bra.uni WDN_%=;\n\tbra.uni WL_%=;\n\tWDN_%=:\n\t}"                    \
            :: "r"(_m), "r"(_p) : "memory");                                           \
    }                                                                                  \
} while (0)

// cp.async 16B with zero-fill (src_size = 0 or 16)
#define CP_ASYNC16(dst, src, sz) \
    asm volatile("cp.async.ca.shared.global [%0], [%1], 16, %2;" \
                 :: "r"((uint32_t)(dst)), "l"(src), "r"((uint32_t)(sz)) : "memory")
#define CP_COMMIT()  asm volatile("cp.async.commit_group;" ::: "memory")
#define CP_WAIT0()   asm volatile("cp.async.wait_group 0;" ::: "memory")

// m16n8k8 tf32 HMMA (sm_80+ baseline ISA)
#define MMA8(d, a, bq)                                                                 \
    asm volatile("mma.sync.aligned.m16n8k8.row.col.f32.tf32.tf32.f32 "                 \
        "{%0,%1,%2,%3}, {%4,%5,%6,%7}, {%8,%9}, {%0,%1,%2,%3};"                        \
        : "+f"((d)[0]), "+f"((d)[1]), "+f"((d)[2]), "+f"((d)[3])                       \
        : "r"(__float_as_uint((a)[0])), "r"(__float_as_uint((a)[1])),                  \
          "r"(__float_as_uint((a)[2])), "r"(__float_as_uint((a)[3])),                  \
          "r"(__float_as_uint((bq).x)), "r"(__float_as_uint((bq).y)))

#define LOAD_A(sl, Abase, ss) do {                                                     \
    const float* _Ap = (Abase) + (ss) * 8 * XST;                                       \
    _Pragma("unroll") for (int _mi = 0; _mi < 4; _mi++) {                              \
        a[sl][_mi][0] = _Ap[_mi * 16];                                                 \
        a[sl][_mi][1] = _Ap[_mi * 16 + 8];                                             \
        a[sl][_mi][2] = _Ap[_mi * 16 + 4 * XST];                                       \
        a[sl][_mi][3] = _Ap[_mi * 16 + 8 + 4 * XST];                                   \
    }                                                                                  \
} while (0)
#define LOAD_B(sl, Bbase, ss) do {                                                     \
    const float2* _Bp = (Bbase) + (ss) * 512;                                          \
    _Pragma("unroll") for (int _ni = 0; _ni < 8; _ni++) bq[sl][_ni] = _Bp[_ni * 32];   \
} while (0)
#define LOAD_FRAGS(sl, Abase, Bbase, ss) do { LOAD_B(sl, Bbase, ss); LOAD_A(sl, Abase, ss); } while (0)

// ---------- prepass: weights -> per-thread B fragment images ----------
__global__ void prep_w(const float* __restrict__ wt) {
    int i = blockIdx.x * blockDim.x + threadIdx.x;   // one float2 per thread
    if (i >= 9 * 8 * 16 * 32) return;
    int tap = i >> 12;
    int r = i & 4095;
    int s = r >> 9;
    int g = (r >> 5) & 15;
    int lane = r & 31;
    int o = g * 8 + (lane >> 2);
    int k0 = s * 8 + (lane & 3);
    float2 v;
    v.x = tf32r(wt[o * 576 + k0 * 9 + tap]);          // wt[o][ci][kh][kw], tap = kh*3+kw
    v.y = tf32r(wt[o * 576 + (k0 + 4) * 9 + tap]);
    ((float2*)g_Wf)[i] = v;
}

// ---------- main kernel: one CTA per (b, h-pair), 256 threads / 8 warps ----------
__global__ __launch_bounds__(256, 1)
void patchconv_mma(const float* __restrict__ x, const float* __restrict__ bias,
                   float* __restrict__ out) {
    extern __shared__ __align__(16) char smem[];
    float* sxs   = (float*)(smem + SM_XS);    // [r(4)][ci(64)][w(136)], w idx = xcol+4
    float* scs   = (float*)(smem + SM_CS);    // channel sums [r][w]
    float* sbias = (float*)(smem + SM_BIAS);
    const uint32_t sb  = smem_u32(smem);
    const uint32_t wb0 = sb + SM_MB,      wb1 = sb + SM_MB + 8;
    const uint32_t cb0 = sb + SM_MB + 16, cb1 = sb + SM_MB + 24;
    const uint32_t rmb = sb + SM_MB + 32, smb = sb + SM_MB + 40;

    const int tid = threadIdx.x, lane = tid & 31, wid = tid >> 5;
    const int h0 = blockIdx.x * 2, b = blockIdx.y;

    if (tid == 0) {
        MB_INIT(wb0, 1); MB_INIT(wb1, 1); MB_INIT(cb0, 8); MB_INIT(cb1, 8);
        MB_INIT(rmb, 256); MB_INIT(smb, 256);
    }
    if (tid < 128) sbias[tid] = bias[tid];
    __syncthreads();
    if (tid == 0) { MB_EXPECT(wb0, WBYTES); BULK_G2S(sb + SM_W, (const void*)g_Wf, WBYTES, wb0); }

    const float* xb = x + (size_t)b * CIN * HD * WD;

    // ---- rows 2,3 (hr = h0+1, h0+2): fire-and-forget cp.async, raw; rounded at t==1 ----
    // chunk id -> (rr, ci, c): 34 16B-chunks/row; c==0 and c==33 are zero halo (sz=0 fill).
    #pragma unroll
    for (int it = 0; it < 17; it++) {
        int id = tid + it * 256;                 // 17*256 = 4352 = 2*64*34
        int c  = id % 34;
        int ci = (id / 34) & 63;
        int rr = id / (34 * 64);                 // 0 -> row2, 1 -> row3
        int hr = h0 + 1 + rr;
        bool ok = (hr < 128) && (c >= 1) && (c <= 32);
        uint32_t dst = sb + SM_XS + (((2 + rr) * 64 + ci) * XST + c * 4) * 4;
        const float* src = ok ? (xb + ((size_t)ci * HD + hr) * WD + (c * 4 - 4)) : xb;
        CP_ASYNC16(dst, src, ok ? 16 : 0);
    }
    CP_COMMIT();

    // ---- rows 0,1 (hr = h0-1, h0): LDG + rna rounding (needed by taps 0-2) ----
    for (int idx = wid; idx < 2 * 64; idx += 8) {
        int r = idx >> 6, ci = idx & 63;
        int hr = h0 - 1 + r;
        float4 v = make_float4(0.f, 0.f, 0.f, 0.f);
        if ((unsigned)hr < 128u)
            v = *(const float4*)(xb + ((size_t)ci * HD + hr) * WD + lane * 4);
        v.x = tf32r(v.x); v.y = tf32r(v.y); v.z = tf32r(v.z); v.w = tf32r(v.w);
        float* d = sxs + (r * 64 + ci) * XST;
        *(float4*)(d + 4 + lane * 4) = v;
        if (lane < 2) *(float4*)(d + lane * 132) = make_float4(0.f, 0.f, 0.f, 0.f);
    }
    __syncthreads();

    // ---- main loop: 9 taps, warp tile 64M x 64N, no CTA barriers ----
    const int warp_m = wid >> 1, warp_n = wid & 1;
    const int hl = warp_m >> 1;
    const int wb = (warp_m & 1) * 64;
    const int ob = warp_n * 64;

    float acc[4][8][4];
    #pragma unroll
    for (int mi = 0; mi < 4; mi++)
        #pragma unroll
        for (int ni = 0; ni < 8; ni++)
            #pragma unroll
            for (int j = 0; j < 4; j++) acc[mi][ni][j] = 0.f;

    float a[2][4][4];
    float2 bq[2][8];

    // prologue: wait tap-0 weights, load step-0 frags into slot 0
    MB_WAIT(wb0, 0);
    {
        const float*  Ab = sxs + hl * 64 * XST + (lane & 3) * XST + wb + 3 + (lane >> 2);
        const float2* Bb = (const float2*)(smem + SM_W) + warp_n * 256 + lane;
        LOAD_FRAGS(0, Ab, Bb, 0);
    }

    #pragma unroll 1
    for (int t = 0; t < 9; t++) {
        const int buf = t & 1;

        if (t == 1) {
            // each thread rounds exactly the chunks it DMA'd (per-thread wait, no barrier)
            CP_WAIT0();
            #pragma unroll
            for (int it = 0; it < 17; it++) {
                int id = tid + it * 256;
                int c  = id % 34;
                int ci = (id / 34) & 63;
                int rr = id / (34 * 64);
                float4* p = (float4*)(sxs + ((2 + rr) * 64 + ci) * XST + c * 4);
                float4 v = *p;
                v.x = tf32r(v.x); v.y = tf32r(v.y); v.z = tf32r(v.z); v.w = tf32r(v.w);
                *p = v;
            }
            MB_ARRIVE_REL(rmb);
        }
        if (t == 3) {
            // channel sums, warp-ownership distributed (rows rounded: own rmb-acquire at t==2 s==7)
            #pragma unroll
            for (int i = 0; i < 3; i++) {
                int idx = i * 32 + lane;
                if (idx < 68) {
                    int p = wid * 68 + idx;
                    int r = p / 136, w = p - r * 136;
                    float s = 0.f;
                    const float* cch = sxs + r * 64 * XST + w;
                    #pragma unroll 8
                    for (int k = 0; k < 64; k++) s += cch[k * XST];
                    scs[p] = s;
                }
            }
            MB_ARRIVE_REL(smb);
        }

        // tid0: refill other buffer with tap t+1 weights once all warps consumed it
        if (t < 8 && tid == 0) {
            const uint32_t nbm = buf ? wb0 : wb1;
            const uint32_t ncb = buf ? cb0 : cb1;
            if (t >= 1) MB_WAIT(ncb, ((t - 1) >> 1) & 1);
            MB_EXPECT(nbm, WBYTES);
            BULK_G2S(sb + SM_W + (buf ^ 1) * WBYTES, (const void*)(g_Wf + (t + 1) * 8192), WBYTES, nbm);
        }

        const int kh = t / 3, kw = t - kh * 3;
        const float*  Ab = sxs + (hl + kh) * 64 * XST + (lane & 3) * XST + wb + kw + 3 + (lane >> 2);
        const float2* Bb = (const float2*)(smem + SM_W + buf * WBYTES) + warp_n * 256 + lane;

        #pragma unroll
        for (int s = 0; s < 8; s++) {
            const int cur = s & 1, nxt = cur ^ 1;
            if (s < 7) {
                LOAD_FRAGS(nxt, Ab, Bb, s + 1);
            } else {
                // all B-frag reads of tap t issued -> signal buffer consumed
                if (lane == 0) MB_ARRIVE(buf ? cb1 : cb0);
                if (t < 8) {
                    MB_WAIT(buf ? wb0 : wb1, ((t + 1) >> 1) & 1);   // tap t+1 weights
                    if (t == 2) MB_WAIT(rmb, 0);                    // row 2 rounded (first touch)
                    const int nt = t + 1, nkh = nt / 3, nkw = nt - nkh * 3;
                    const float*  An = sxs + (hl + nkh) * 64 * XST + (lane & 3) * XST + wb + nkw + 3 + (lane >> 2);
                    const float2* Bn = (const float2*)(smem + SM_W + (nt & 1) * WBYTES) + warp_n * 256 + lane;
                    LOAD_FRAGS(nxt, An, Bn, 0);
                }
            }
            #pragma unroll
            for (int mi = 0; mi < 4; mi++)
                #pragma unroll
                for (int ni = 0; ni < 8; ni++)
                    MMA8(acc[mi][ni], a[cur][mi], bq[cur][ni]);
        }
    }

    // ---- epilogue: inline patch-sum windows + bias + rank-1, sector-aligned stores ----
    MB_WAIT(smb, 0);
    const int hg = h0 + hl;
    float* outb = out + (size_t)b * OC * HD * WD + (size_t)hg * WD;
    #pragma unroll
    for (int mi = 0; mi < 4; mi++) {
        int w0r = wb + mi * 16 + (lane >> 2);
        float s0 = 0.f, s1 = 0.f;
        #pragma unroll
        for (int kh2 = 0; kh2 < 3; kh2++)
            #pragma unroll
            for (int kw2 = 0; kw2 < 3; kw2++) {
                s0 += scs[(hl + kh2) * XST + w0r + kw2 + 3];
                s1 += scs[(hl + kh2) * XST + w0r + 8 + kw2 + 3];
            }
        float c0 = 0.1f * (float)(hg + w0r) * s0;
        float c1 = 0.1f * (float)(hg + w0r + 8) * s1;
        #pragma unroll
        for (int ni = 0; ni < 8; ni++) {
            int o = ob + ni * 8 + (lane & 3) * 2;
            float bz0 = sbias[o], bz1 = sbias[o + 1];
            float* p0 = outb + (size_t)o * (HD * WD);
            float* p1 = p0 + HD * WD;
            p0[w0r]     = acc[mi][ni][0] + c0 + bz0;
            p1[w0r]     = acc[mi][ni][1] + c0 + bz1;
            p0[w0r + 8] = acc[mi][ni][2] + c1 + bz0;
            p1[w0r + 8] = acc[mi][ni][3] + c1 + bz1;
        }
    }
}

extern "C" void kernel_launch(void* const* d_in, const int* in_sizes, int n_in,
                              void* d_out, int out_size) {
    const float* x    = (const float*)d_in[0];
    const float* wt   = (const float*)d_in[1];
    const float* bias = (const float*)d_in[2];
    float* out        = (float*)d_out;
    cudaFuncSetAttribute(patchconv_mma, cudaFuncAttributeMaxDynamicSharedMemorySize, SM_TOT);
    prep_w<<<(9 * 8 * 16 * 32 + 255) / 256, 256>>>(wt);
    patchconv_mma<<<dim3(64, 16), 256, SM_TOT>>>(x, bias, out);
}

// round 13
// speedup vs baseline: 1.9206x; 1.0639x over previous
#include <cuda_runtime.h>
#include <cstdint>

#define HD 128
#define WD 128
#define OC 128
#define CIN 64
#define XST 136                 // x smem row stride (floats): conflict-free frag reads
#define WBYTES 32768            // one tap of pre-arranged B fragments

// smem byte offsets
#define SM_XS   0               // 4 * 64 * 136 * 4 = 139264
#define SM_W    139264          // 2 * 32768 = 65536
#define SM_CS   204800          // 4 * 136 * 4 = 2176
#define SM_PS   206976          // 2 * 128 * 4 = 1024
#define SM_BIAS 208000          // 512
#define SM_MB   208512          // wb0, wb1, cb0, cb1
#define SM_TOT  208560

// B fragments, register-image order: [tap][s(8)][g(16)][lane(32)][2]
__device__ __align__(128) float g_Wf[9 * 8 * 16 * 32 * 2];

// ---------- helpers ----------
__device__ __forceinline__ uint32_t smem_u32(const void* p) {
    uint32_t a;
    asm("{ .reg .u64 t; cvta.to.shared.u64 t, %1; cvt.u32.u64 %0, t; }" : "=r"(a) : "l"(p));
    return a;
}
__device__ __forceinline__ float tf32r(float v) {
    float r; asm("cvt.rna.tf32.f32 %0, %1;" : "=f"(r) : "f"(v)); return r;
}
#define MB_INIT(mb, c)   asm volatile("mbarrier.init.shared.b64 [%0], %1;" :: "r"(mb), "r"((uint32_t)(c)) : "memory")
#define MB_EXPECT(mb, n) asm volatile("mbarrier.arrive.expect_tx.shared.b64 _, [%0], %1;" :: "r"(mb), "r"((uint32_t)(n)) : "memory")
#define MB_ARRIVE(mb)    asm volatile("mbarrier.arrive.shared.b64 _, [%0];" :: "r"(mb) : "memory")
#define BULK_G2S(dst, src, n, mb) \
    asm volatile("cp.async.bulk.shared::cta.global.mbarrier::complete_tx::bytes [%0], [%1], %2, [%3];" \
                 :: "r"(dst), "l"(src), "r"((uint32_t)(n)), "r"(mb) : "memory")
#define MB_WAIT(mb, par) do {                                                          \
    uint32_t _m = (mb), _p = (par), _d;                                                \
    asm volatile("{\n\t.reg .pred p;\n\t"                                              \
        "mbarrier.try_wait.parity.acquire.cta.shared::cta.b64 p, [%1], %2;\n\t"        \
        "selp.b32 %0,1,0,p;\n\t}" : "=r"(_d) : "r"(_m), "r"(_p) : "memory");           \
    if (!_d) {                                                                         \
        asm volatile("{\n\t.reg .pred P1;\n\tWL_%=:\n\t"                               \
            "mbarrier.try_wait.parity.acquire.cta.shared::cta.b64 P1, [%0], %1, 0x989680;\n\t" \
            "@P1 bra.uni WDN_%=;\n\tbra.uni WL_%=;\n\tWDN_%=:\n\t}"                    \
            :: "r"(_m), "r"(_p) : "memory");                                           \
    }                                                                                  \
} while (0)

// m16n8k8 tf32 HMMA (sm_80+ baseline ISA)
#define MMA8(d, a, bq)                                                                 \
    asm volatile("mma.sync.aligned.m16n8k8.row.col.f32.tf32.tf32.f32 "                 \
        "{%0,%1,%2,%3}, {%4,%5,%6,%7}, {%8,%9}, {%0,%1,%2,%3};"                        \
        : "+f"((d)[0]), "+f"((d)[1]), "+f"((d)[2]), "+f"((d)[3])                       \
        : "r"(__float_as_uint((a)[0])), "r"(__float_as_uint((a)[1])),                  \
          "r"(__float_as_uint((a)[2])), "r"(__float_as_uint((a)[3])),                  \
          "r"(__float_as_uint((bq).x)), "r"(__float_as_uint((bq).y)))

#define LOAD_A(sl, Abase, ss) do {                                                     \
    const float* _Ap = (Abase) + (ss) * 8 * XST;                                       \
    _Pragma("unroll") for (int _mi = 0; _mi < 4; _mi++) {                              \
        a[sl][_mi][0] = _Ap[_mi * 16];                                                 \
        a[sl][_mi][1] = _Ap[_mi * 16 + 8];                                             \
        a[sl][_mi][2] = _Ap[_mi * 16 + 4 * XST];                                       \
        a[sl][_mi][3] = _Ap[_mi * 16 + 8 + 4 * XST];                                   \
    }                                                                                  \
} while (0)
#define LOAD_B(sl, Bbase, ss) do {                                                     \
    const float2* _Bp = (Bbase) + (ss) * 512;                                          \
    _Pragma("unroll") for (int _ni = 0; _ni < 8; _ni++) bq[sl][_ni] = _Bp[_ni * 32];   \
} while (0)
#define LOAD_FRAGS(sl, Abase, Bbase, ss) do { LOAD_B(sl, Bbase, ss); LOAD_A(sl, Abase, ss); } while (0)

// one tap's 8 k-steps; REVV=1 traverses steps 7..0 (order-independent K sum).
// Paired warps on the same SMSP run opposite orders -> decorrelated stalls.
#define TAP_BODY(REVV)                                                                 \
    _Pragma("unroll")                                                                  \
    for (int ss = 0; ss < 8; ss++) {                                                   \
        const int cur = ss & 1, nxt = cur ^ 1;                                         \
        if (ss < 7) {                                                                  \
            LOAD_FRAGS(nxt, Ab, Bb, (REVV) ? (6 - ss) : (ss + 1));                     \
        } else {                                                                       \
            if (lane == 0) MB_ARRIVE(buf ? cb1 : cb0);                                 \
            if (t < 8) {                                                               \
                MB_WAIT(buf ? wb0 : wb1, ((t + 1) >> 1) & 1);                          \
                const int nt = t + 1, nkh = nt / 3, nkw = nt - nkh * 3;                \
                const float*  An = sxs + (hl + nkh) * 64 * XST + (lane & 3) * XST      \
                                   + wb + nkw + 3 + (lane >> 2);                       \
                const float2* Bn = (const float2*)(smem + SM_W + (nt & 1) * WBYTES)    \
                                   + warp_n * 256 + lane;                              \
                LOAD_FRAGS(nxt, An, Bn, (REVV) ? 7 : 0);                               \
            }                                                                          \
        }                                                                              \
        _Pragma("unroll")                                                              \
        for (int mi = 0; mi < 4; mi++)                                                 \
            _Pragma("unroll")                                                          \
            for (int ni = 0; ni < 8; ni++)                                             \
                MMA8(acc[mi][ni], a[cur][mi], bq[cur][ni]);                            \
    }

// ---------- prepass: weights -> per-thread B fragment images ----------
__global__ void prep_w(const float* __restrict__ wt) {
    int i = blockIdx.x * blockDim.x + threadIdx.x;   // one float2 per thread
    if (i >= 9 * 8 * 16 * 32) return;
    int tap = i >> 12;
    int r = i & 4095;
    int s = r >> 9;
    int g = (r >> 5) & 15;
    int lane = r & 31;
    int o = g * 8 + (lane >> 2);
    int k0 = s * 8 + (lane & 3);
    float2 v;
    v.x = tf32r(wt[o * 576 + k0 * 9 + tap]);          // wt[o][ci][kh][kw], tap = kh*3+kw
    v.y = tf32r(wt[o * 576 + (k0 + 4) * 9 + tap]);
    ((float2*)g_Wf)[i] = v;
}

// ---------- main kernel: one CTA per (b, h-pair), 256 threads / 8 warps ----------
__global__ __launch_bounds__(256, 1)
void patchconv_mma(const float* __restrict__ x, const float* __restrict__ bias,
                   float* __restrict__ out) {
    extern __shared__ __align__(16) char smem[];
    float* sxs   = (float*)(smem + SM_XS);    // [r(4)][ci(64)][w(136)], w idx = xcol+4
    float* scs   = (float*)(smem + SM_CS);    // channel sums [r][w]
    float* sps   = (float*)(smem + SM_PS);    // 3x3 patch sums [hl][w]
    float* sbias = (float*)(smem + SM_BIAS);
    const uint32_t sb  = smem_u32(smem);
    const uint32_t wb0 = sb + SM_MB,      wb1 = sb + SM_MB + 8;
    const uint32_t cb0 = sb + SM_MB + 16, cb1 = sb + SM_MB + 24;

    const int tid = threadIdx.x, lane = tid & 31, wid = tid >> 5;
    const int h0 = blockIdx.x * 2, b = blockIdx.y;

    if (tid == 0) { MB_INIT(wb0, 1); MB_INIT(wb1, 1); MB_INIT(cb0, 8); MB_INIT(cb1, 8); }
    if (tid < 128) sbias[tid] = bias[tid];
    __syncthreads();
    if (tid == 0) { MB_EXPECT(wb0, WBYTES); BULK_G2S(sb + SM_W, (const void*)g_Wf, WBYTES, wb0); }

    // ---- stage x: 4 halo rows, tf32-rounded, zero borders ----
    const float* xb = x + (size_t)b * CIN * HD * WD;
    for (int idx = wid; idx < 4 * 64; idx += 8) {
        int r = idx >> 6, ci = idx & 63;
        int hr = h0 - 1 + r;
        float4 v = make_float4(0.f, 0.f, 0.f, 0.f);
        if ((unsigned)hr < 128u)
            v = *(const float4*)(xb + ((size_t)ci * HD + hr) * WD + lane * 4);
        v.x = tf32r(v.x); v.y = tf32r(v.y); v.z = tf32r(v.z); v.w = tf32r(v.w);
        float* d = sxs + (r * 64 + ci) * XST;
        *(float4*)(d + 4 + lane * 4) = v;
        if (lane < 2) *(float4*)(d + lane * 132) = make_float4(0.f, 0.f, 0.f, 0.f);
    }
    __syncthreads();

    // ---- channel sums + 3x3 patch sums (rank-1 term) ----
    for (int p = tid; p < 4 * XST; p += 256) {
        int r = p / XST, w = p - r * XST;
        float s = 0.f;
        const float* c = sxs + r * 64 * XST + w;
        #pragma unroll 8
        for (int k = 0; k < 64; k++) s += c[k * XST];
        scs[p] = s;
    }
    __syncthreads();
    {
        int hl = tid >> 7, wo = tid & 127;
        float s = 0.f;
        #pragma unroll
        for (int kh = 0; kh < 3; kh++)
            #pragma unroll
            for (int kw = 0; kw < 3; kw++)
                s += scs[(hl + kh) * XST + wo + kw + 3];
        sps[tid] = s;
    }
    __syncthreads();

    // ---- main loop: 9 taps, warp tile 64M x 64N, no CTA barriers ----
    const int warp_m = wid >> 1, warp_n = wid & 1;
    const int hl = warp_m >> 1;
    const int wb = (warp_m & 1) * 64;
    const int ob = warp_n * 64;
    const bool rev = (wid >= 4);     // SMSP partner warp runs reversed step order

    float acc[4][8][4];
    #pragma unroll
    for (int mi = 0; mi < 4; mi++)
        #pragma unroll
        for (int ni = 0; ni < 8; ni++)
            #pragma unroll
            for (int j = 0; j < 4; j++) acc[mi][ni][j] = 0.f;

    float a[2][4][4];
    float2 bq[2][8];

    // prologue: wait tap-0 weights, load first-step frags into slot 0
    MB_WAIT(wb0, 0);
    {
        const float*  Ab = sxs + hl * 64 * XST + (lane & 3) * XST + wb + 3 + (lane >> 2);
        const float2* Bb = (const float2*)(smem + SM_W) + warp_n * 256 + lane;
        if (rev) { LOAD_FRAGS(0, Ab, Bb, 7); } else { LOAD_FRAGS(0, Ab, Bb, 0); }
    }

    #pragma unroll 1
    for (int t = 0; t < 9; t++) {
        const int buf = t & 1;
        // tid0: refill other buffer with tap t+1 weights once all warps consumed it
        if (t < 8 && tid == 0) {
            const uint32_t nbm = buf ? wb0 : wb1;
            const uint32_t ncb = buf ? cb0 : cb1;
            if (t >= 1) MB_WAIT(ncb, ((t - 1) >> 1) & 1);
            MB_EXPECT(nbm, WBYTES);
            BULK_G2S(sb + SM_W + (buf ^ 1) * WBYTES, (const void*)(g_Wf + (t + 1) * 8192), WBYTES, nbm);
        }

        const int kh = t / 3, kw = t - kh * 3;
        const float*  Ab = sxs + (hl + kh) * 64 * XST + (lane & 3) * XST + wb + kw + 3 + (lane >> 2);
        const float2* Bb = (const float2*)(smem + SM_W + buf * WBYTES) + warp_n * 256 + lane;

        if (rev) { TAP_BODY(1) } else { TAP_BODY(0) }
    }

    // ---- epilogue: + bias[o] + 0.1*(h+w)*patch_sum, 32B-sector-aligned stores ----
    const int hg = h0 + hl;
    float* outb = out + (size_t)b * OC * HD * WD + (size_t)hg * WD;
    #pragma unroll
    for (int mi = 0; mi < 4; mi++) {
        int w0r = wb + mi * 16 + (lane >> 2);
        float c0 = 0.1f * (float)(hg + w0r) * sps[hl * 128 + w0r];
        float c1 = 0.1f * (float)(hg + w0r + 8) * sps[hl * 128 + w0r + 8];
        #pragma unroll
        for (int ni = 0; ni < 8; ni++) {
            int o = ob + ni * 8 + (lane & 3) * 2;
            float bz0 = sbias[o], bz1 = sbias[o + 1];
            float* p0 = outb + (size_t)o * (HD * WD);
            float* p1 = p0 + HD * WD;
            p0[w0r]     = acc[mi][ni][0] + c0 + bz0;
            p1[w0r]     = acc[mi][ni][1] + c0 + bz1;
            p0[w0r + 8] = acc[mi][ni][2] + c1 + bz0;
            p1[w0r + 8] = acc[mi][ni][3] + c1 + bz1;
        }
    }
}

extern "C" void kernel_launch(void* const* d_in, const int* in_sizes, int n_in,
                              void* d_out, int out_size) {
    const float* x    = (const float*)d_in[0];
    const float* wt   = (const float*)d_in[1];
    const float* bias = (const float*)d_in[2];
    float* out        = (float*)d_out;
    cudaFuncSetAttribute(patchconv_mma, cudaFuncAttributeMaxDynamicSharedMemorySize, SM_TOT);
    prep_w<<<(9 * 8 * 16 * 32 + 255) / 256, 256>>>(wt);
    patchconv_mma<<<dim3(64, 16), 256, SM_TOT>>>(x, bias, out);
}

// round 15
// speedup vs baseline: 2.1731x; 1.1315x over previous
#include <cuda_runtime.h>
#include <cstdint>

#define HD 128
#define WD 128
#define OC 128
#define CIN 64
#define HW (HD * WD)
#define XW 136                  // xbf word stride per ci2-row: 8q+w' distinct mod 32
#define WBYTES 16384            // one tap of B frag images (bf16)

// smem byte offsets
#define SM_XB   0               // 4 * 32 * 136 * 4 = 69632
#define SM_W    69632           // 2 * 16384 = 32768
#define SM_CS   102400          // 4 * 136 * 4 = 2176
#define SM_PS   104576          // 2 * 128 * 4 = 1024
#define SM_BIAS 105600          // 512
#define SM_MB   106112          // wb0, wb1, cb0, cb1
#define SM_TOT  106144

// B fragments (bf16), register-image order: [tap][s(4)][g(16)][lane(32)][2 words]
__device__ __align__(128) unsigned g_Wf[9 * 4 * 16 * 32 * 2];

// ---------- helpers ----------
__device__ __forceinline__ uint32_t smem_u32(const void* p) {
    uint32_t a;
    asm("{ .reg .u64 t; cvta.to.shared.u64 t, %1; cvt.u32.u64 %0, t; }" : "=r"(a) : "l"(p));
    return a;
}
__device__ __forceinline__ unsigned pack_bf2(float lo, float hi) {
    unsigned r;
    asm("cvt.rn.bf16x2.f32 %0, %1, %2;" : "=r"(r) : "f"(hi), "f"(lo));  // low = %2
    return r;
}
#define MB_INIT(mb, c)   asm volatile("mbarrier.init.shared.b64 [%0], %1;" :: "r"(mb), "r"((uint32_t)(c)) : "memory")
#define MB_EXPECT(mb, n) asm volatile("mbarrier.arrive.expect_tx.shared.b64 _, [%0], %1;" :: "r"(mb), "r"((uint32_t)(n)) : "memory")
#define MB_ARRIVE(mb)    asm volatile("mbarrier.arrive.shared.b64 _, [%0];" :: "r"(mb) : "memory")
#define BULK_G2S(dst, src, n, mb) \
    asm volatile("cp.async.bulk.shared::cta.global.mbarrier::complete_tx::bytes [%0], [%1], %2, [%3];" \
                 :: "r"(dst), "l"(src), "r"((uint32_t)(n)), "r"(mb) : "memory")
#define MB_WAIT(mb, par) do {                                                          \
    uint32_t _m = (mb), _p = (par), _d;                                                \
    asm volatile("{\n\t.reg .pred p;\n\t"                                              \
        "mbarrier.try_wait.parity.acquire.cta.shared::cta.b64 p, [%1], %2;\n\t"        \
        "selp.b32 %0,1,0,p;\n\t}" : "=r"(_d) : "r"(_m), "r"(_p) : "memory");           \
    if (!_d) {                                                                         \
        asm volatile("{\n\t.reg .pred P1;\n\tWL_%=:\n\t"                               \
            "mbarrier.try_wait.parity.acquire.cta.shared::cta.b64 P1, [%0], %1, 0x989680;\n\t" \
            "@P1 bra.uni WDN_%=;\n\tbra.uni WL_%=;\n\tWDN_%=:\n\t}"                    \
            :: "r"(_m), "r"(_p) : "memory");                                           \
    }                                                                                  \
} while (0)

// m16n8k16 bf16 HMMA (sm_80+ baseline ISA): A 4 regs, B 2 regs, D 4 f32
#define MMA16(d, av, bv)                                                               \
    asm volatile("mma.sync.aligned.m16n8k16.row.col.f32.bf16.bf16.f32 "                \
        "{%0,%1,%2,%3}, {%4,%5,%6,%7}, {%8,%9}, {%0,%1,%2,%3};"                        \
        : "+f"((d)[0]), "+f"((d)[1]), "+f"((d)[2]), "+f"((d)[3])                       \
        : "r"((av)[0]), "r"((av)[1]), "r"((av)[2]), "r"((av)[3]),                      \
          "r"((bv)[0]), "r"((bv)[1]))

// A frags for k-step ss of current tap: base xw + ((row*32 + ss*8 + lane&3)*136 + woff)
#define LOAD_A(sl, rowci2, woff, ss) do {                                              \
    const unsigned* _p = xw + ((rowci2) + (ss) * 8 + (lane & 3)) * XW + (woff);        \
    _Pragma("unroll") for (int _mi = 0; _mi < 4; _mi++) {                              \
        const unsigned* _q = _p + _mi * 16;                                            \
        a[sl][_mi][0] = _q[0];                                                         \
        a[sl][_mi][1] = _q[8];                                                         \
        a[sl][_mi][2] = _q[4 * XW];                                                    \
        a[sl][_mi][3] = _q[8 + 4 * XW];                                                \
    }                                                                                  \
} while (0)
// B frags: image [s][g][lane][2]; warp window g = warp_n*8 + ni
#define LOAD_B(sl, Bbase, ss) do {                                                     \
    const uint2* _bp = (const uint2*)(Bbase) + ((ss) * 16) * 32 + lane;                \
    _Pragma("unroll") for (int _ni = 0; _ni < 8; _ni++) {                              \
        uint2 _v = _bp[_ni * 32];                                                      \
        b[sl][_ni][0] = _v.x; b[sl][_ni][1] = _v.y;                                    \
    }                                                                                  \
} while (0)
#define LOAD_FRAGS(sl, rowci2, woff, Bbase, ss) \
    do { LOAD_B(sl, Bbase, ss); LOAD_A(sl, rowci2, woff, ss); } while (0)

// ---------- prepass: weights -> bf16 m16n8k16 B-frag images ----------
__global__ void prep_w(const float* __restrict__ wt) {
    int i = blockIdx.x * blockDim.x + threadIdx.x;   // word index
    if (i >= 9 * 4 * 16 * 32 * 2) return;
    int jb   = i & 1;
    int lane = (i >> 1) & 31;
    int g    = (i >> 6) & 15;
    int s    = (i >> 10) & 3;
    int tap  = i >> 12;
    int o   = g * 8 + (lane >> 2);
    int ci0 = s * 16 + jb * 8 + 2 * (lane & 3);
    float v0 = wt[o * 576 + ci0 * 9 + tap];          // wt[o][ci][kh][kw], tap = kh*3+kw
    float v1 = wt[o * 576 + (ci0 + 1) * 9 + tap];
    g_Wf[i] = pack_bf2(v0, v1);
}

// ---------- main kernel: one CTA per (b, h-pair), 256 threads / 8 warps ----------
__global__ __launch_bounds__(256, 1)
void patchconv_mma(const float* __restrict__ x, const float* __restrict__ bias,
                   float* __restrict__ out) {
    extern __shared__ __align__(16) char smem[];
    unsigned* xw  = (unsigned*)(smem + SM_XB);  // [r(4)][ci2(32)][w(136)] bf16x2, w = xcol+1
    float* scs    = (float*)(smem + SM_CS);     // EXACT fp32 channel sums [r][w(136)]
    float* sps    = (float*)(smem + SM_PS);     // 3x3 patch sums [hl][w0]
    float* sbias  = (float*)(smem + SM_BIAS);
    const uint32_t sb  = smem_u32(smem);
    const uint32_t wb0 = sb + SM_MB,      wb1 = sb + SM_MB + 8;
    const uint32_t cb0 = sb + SM_MB + 16, cb1 = sb + SM_MB + 24;

    const int tid = threadIdx.x, lane = tid & 31, wid = tid >> 5;
    const int h0 = blockIdx.x * 2, bb = blockIdx.y;

    if (tid == 0) { MB_INIT(wb0, 1); MB_INIT(wb1, 1); MB_INIT(cb0, 8); MB_INIT(cb1, 8); }
    if (tid < 128) sbias[tid] = bias[tid];
    __syncthreads();
    if (tid == 0) { MB_EXPECT(wb0, WBYTES); BULK_G2S(sb + SM_W, (const void*)g_Wf, WBYTES, wb0); }

    // ---- stage x: transpose to [r][ci2][w] bf16x2 + EXACT fp32 channel sums ----
    const float* xb = x + (size_t)bb * CIN * HW;
    for (int u = wid; u < 20; u += 8) {                 // 4 rows x 5 w-chunks
        int r = u / 5, wc = u - r * 5;
        int w = wc * 32 + lane;                         // w = xcol + 1
        if (w < XW) {
            int hr = h0 - 1 + r;
            int xcol = w - 1;
            bool ok = (w < 131) && ((unsigned)hr < 128u) && ((unsigned)xcol < 128u);
            const float* sp = xb + (size_t)hr * WD + xcol;
            float cs = 0.f;
            unsigned* dst = xw + (r * 32) * XW + w;
            #pragma unroll 4
            for (int c2 = 0; c2 < 32; c2++) {
                float v0 = 0.f, v1 = 0.f;
                if (ok) {
                    v0 = __ldg(sp + (size_t)(2 * c2) * HW);
                    v1 = __ldg(sp + (size_t)(2 * c2 + 1) * HW);
                }
                cs += v0 + v1;
                dst[c2 * XW] = pack_bf2(v0, v1);
            }
            scs[r * XW + w] = cs;
        }
    }
    __syncthreads();
    {   // patch sums: output (hl, w0) <- sum cs[(hl+kh)][w0+kw]
        int hl = tid >> 7, wo = tid & 127;
        float s = 0.f;
        #pragma unroll
        for (int kh = 0; kh < 3; kh++)
            #pragma unroll
            for (int kw = 0; kw < 3; kw++)
                s += scs[(hl + kh) * XW + wo + kw];
        sps[tid] = s;
    }
    __syncthreads();

    // ---- main loop: 9 taps x 4 k16-steps, warp tile 64M(w) x 64N(o) ----
    const int warp_m = wid >> 1, warp_n = wid & 1;
    const int hl  = warp_m >> 1;
    const int wbq = (warp_m & 1) * 64;
    const int ob  = warp_n * 64;
    const int woffl = wbq + (lane >> 2);       // + kw added per tap (w = xcol+1)
    const unsigned boff = (warp_n * 8) * 32;   // g-window offset in uint2 units

    float acc[4][8][4];
    #pragma unroll
    for (int mi = 0; mi < 4; mi++)
        #pragma unroll
        for (int ni = 0; ni < 8; ni++)
            #pragma unroll
            for (int j = 0; j < 4; j++) acc[mi][ni][j] = 0.f;

    unsigned a[2][4][4];
    unsigned b[2][8][2];

    // prologue: wait tap-0 weights, load step-0 frags into slot 0 (tap0: kh=0, kw=0)
    MB_WAIT(wb0, 0);
    {
        const uint2* Bb = (const uint2*)(smem + SM_W) + boff;
        LOAD_FRAGS(0, hl * 32, woffl, Bb, 0);
    }

    #pragma unroll 1
    for (int t = 0; t < 9; t++) {
        const int buf = t & 1;
        if (t < 8 && tid == 0) {
            const uint32_t nbm = buf ? wb0 : wb1;
            const uint32_t ncb = buf ? cb0 : cb1;
            if (t >= 1) MB_WAIT(ncb, ((t - 1) >> 1) & 1);
            MB_EXPECT(nbm, WBYTES);
            BULK_G2S(sb + SM_W + (buf ^ 1) * WBYTES, (const void*)(g_Wf + (t + 1) * 4096), WBYTES, nbm);
        }

        const int kh = t / 3, kw = t - kh * 3;
        const int rowci2 = (hl + kh) * 32;
        const int woff = woffl + kw;           // w index = w0 + kw (w = xcol+1)
        const uint2* Bb = (const uint2*)(smem + SM_W + buf * WBYTES) + boff;

        #pragma unroll
        for (int s = 0; s < 4; s++) {
            const int cur = s & 1, nxt = cur ^ 1;
            if (s < 3) {
                LOAD_FRAGS(nxt, rowci2, woff, Bb, s + 1);
            } else {
                if (lane == 0) MB_ARRIVE(buf ? cb1 : cb0);
                if (t < 8) {
                    MB_WAIT(buf ? wb0 : wb1, ((t + 1) >> 1) & 1);
                    const int nt = t + 1, nkh = nt / 3, nkw = nt - nkh * 3;
                    const uint2* Bn = (const uint2*)(smem + SM_W + (nt & 1) * WBYTES) + boff;
                    LOAD_FRAGS(nxt, (hl + nkh) * 32, woffl + nkw, Bn, 0);
                }
            }
            #pragma unroll
            for (int mi = 0; mi < 4; mi++)
                #pragma unroll
                for (int ni = 0; ni < 8; ni++)
                    MMA16(acc[mi][ni], a[cur][mi], b[cur][ni]);
        }
    }

    // ---- epilogue: + bias[o] + 0.1*(h+w)*patch_sum (EXACT), 32B-sector stores ----
    const int hg = h0 + hl;
    float* outb = out + (size_t)bb * OC * HW + (size_t)hg * WD;
    #pragma unroll
    for (int mi = 0; mi < 4; mi++) {
        int w0 = wbq + mi * 16 + (lane >> 2);
        float c0 = 0.1f * (float)(hg + w0) * sps[hl * 128 + w0];
        float c1 = 0.1f * (float)(hg + w0 + 8) * sps[hl * 128 + w0 + 8];
        #pragma unroll
        for (int ni = 0; ni < 8; ni++) {
            int o = ob + ni * 8 + 2 * (lane & 3);
            float bz0 = sbias[o], bz1 = sbias[o + 1];
            float* p0 = outb + (size_t)o * HW;
            float* p1 = p0 + HW;
            p0[w0]     = acc[mi][ni][0] + c0 + bz0;
            p1[w0]     = acc[mi][ni][1] + c0 + bz1;
            p0[w0 + 8] = acc[mi][ni][2] + c1 + bz0;
            p1[w0 + 8] = acc[mi][ni][3] + c1 + bz1;
        }
    }
}

extern "C" void kernel_launch(void* const* d_in, const int* in_sizes, int n_in,
                              void* d_out, int out_size) {
    const float* x    = (const float*)d_in[0];
    const float* wt   = (const float*)d_in[1];
    const float* bias = (const float*)d_in[2];
    float* out        = (float*)d_out;
    cudaFuncSetAttribute(patchconv_mma, cudaFuncAttributeMaxDynamicSharedMemorySize, SM_TOT);
    prep_w<<<(9 * 4 * 16 * 32 * 2 + 255) / 256, 256>>>(wt);
    patchconv_mma<<<dim3(64, 16), 256, SM_TOT>>>(x, bias, out);
}

// round 16
// speedup vs baseline: 2.7103x; 1.2472x over previous
#include <cuda_runtime.h>
#include <cstdint>

#define HD 128
#define WD 128
#define OC 128
#define CIN 64
#define HW (HD * WD)
#define XW 136                  // xbf word stride per ci2-row: 8q+w' distinct mod 32
#define WALL 147456             // ALL 9 taps of B frag images (bf16), resident

// smem byte offsets
#define SM_XB   0               // 4 * 32 * 136 * 4 = 69632
#define SM_W    69632           // 147456 (all taps, single buffer)
#define SM_CS   217088          // 4 * 136 * 4 = 2176
#define SM_PS   219264          // 2 * 128 * 4 = 1024
#define SM_BIAS 220288          // 512
#define SM_MB   220800          // wb
#define SM_TOT  220816

// B fragments (bf16), register-image order: [tap][s(4)][g(16)][lane(32)][2 words]
__device__ __align__(128) unsigned g_Wf[9 * 4 * 16 * 32 * 2];

// ---------- helpers ----------
__device__ __forceinline__ uint32_t smem_u32(const void* p) {
    uint32_t a;
    asm("{ .reg .u64 t; cvta.to.shared.u64 t, %1; cvt.u32.u64 %0, t; }" : "=r"(a) : "l"(p));
    return a;
}
__device__ __forceinline__ unsigned pack_bf2(float lo, float hi) {
    unsigned r;
    asm("cvt.rn.bf16x2.f32 %0, %1, %2;" : "=r"(r) : "f"(hi), "f"(lo));  // low = %2
    return r;
}
#define MB_INIT(mb, c)   asm volatile("mbarrier.init.shared.b64 [%0], %1;" :: "r"(mb), "r"((uint32_t)(c)) : "memory")
#define MB_EXPECT(mb, n) asm volatile("mbarrier.arrive.expect_tx.shared.b64 _, [%0], %1;" :: "r"(mb), "r"((uint32_t)(n)) : "memory")
#define BULK_G2S(dst, src, n, mb) \
    asm volatile("cp.async.bulk.shared::cta.global.mbarrier::complete_tx::bytes [%0], [%1], %2, [%3];" \
                 :: "r"(dst), "l"(src), "r"((uint32_t)(n)), "r"(mb) : "memory")
#define MB_WAIT(mb, par) do {                                                          \
    uint32_t _m = (mb), _p = (par), _d;                                                \
    asm volatile("{\n\t.reg .pred p;\n\t"                                              \
        "mbarrier.try_wait.parity.acquire.cta.shared::cta.b64 p, [%1], %2;\n\t"        \
        "selp.b32 %0,1,0,p;\n\t}" : "=r"(_d) : "r"(_m), "r"(_p) : "memory");           \
    if (!_d) {                                                                         \
        asm volatile("{\n\t.reg .pred P1;\n\tWL_%=:\n\t"                               \
            "mbarrier.try_wait.parity.acquire.cta.shared::cta.b64 P1, [%0], %1, 0x989680;\n\t" \
            "@P1 bra.uni WDN_%=;\n\tbra.uni WL_%=;\n\tWDN_%=:\n\t}"                    \
            :: "r"(_m), "r"(_p) : "memory");                                           \
    }                                                                                  \
} while (0)

// m16n8k16 bf16 HMMA (sm_80+ baseline ISA): A 4 regs, B 2 regs, D 4 f32
#define MMA16(d, av, bv)                                                               \
    asm volatile("mma.sync.aligned.m16n8k16.row.col.f32.bf16.bf16.f32 "                \
        "{%0,%1,%2,%3}, {%4,%5,%6,%7}, {%8,%9}, {%0,%1,%2,%3};"                        \
        : "+f"((d)[0]), "+f"((d)[1]), "+f"((d)[2]), "+f"((d)[3])                       \
        : "r"((av)[0]), "r"((av)[1]), "r"((av)[2]), "r"((av)[3]),                      \
          "r"((bv)[0]), "r"((bv)[1]))

// A frags for k-step ss of a tap: base xw + ((rowci2 + ss*8 + lane&3)*136 + woff)
#define LOAD_A(sl, rowci2, woff, ss) do {                                              \
    const unsigned* _p = xw + ((rowci2) + (ss) * 8 + (lane & 3)) * XW + (woff);        \
    _Pragma("unroll") for (int _mi = 0; _mi < 4; _mi++) {                              \
        const unsigned* _q = _p + _mi * 16;                                            \
        a[sl][_mi][0] = _q[0];                                                         \
        a[sl][_mi][1] = _q[8];                                                         \
        a[sl][_mi][2] = _q[4 * XW];                                                    \
        a[sl][_mi][3] = _q[8 + 4 * XW];                                                \
    }                                                                                  \
} while (0)
// B frags for (tap, ss) from the resident image
#define LOAD_B2(sl, tap, ss) do {                                                      \
    const uint2* _bp = (const uint2*)(smem + SM_W + (tap) * 16384)                     \
                       + (ss) * 512 + boff + lane;                                     \
    _Pragma("unroll") for (int _ni = 0; _ni < 8; _ni++) {                              \
        uint2 _v = _bp[_ni * 32];                                                      \
        b[sl][_ni][0] = _v.x; b[sl][_ni][1] = _v.y;                                    \
    }                                                                                  \
} while (0)

// ---------- prepass: weights -> bf16 m16n8k16 B-frag images ----------
__global__ void prep_w(const float* __restrict__ wt) {
    int i = blockIdx.x * blockDim.x + threadIdx.x;   // word index
    if (i >= 9 * 4 * 16 * 32 * 2) return;
    int jb   = i & 1;
    int lane = (i >> 1) & 31;
    int g    = (i >> 6) & 15;
    int s    = (i >> 10) & 3;
    int tap  = i >> 12;
    int o   = g * 8 + (lane >> 2);
    int ci0 = s * 16 + jb * 8 + 2 * (lane & 3);
    float v0 = wt[o * 576 + ci0 * 9 + tap];          // wt[o][ci][kh][kw], tap = kh*3+kw
    float v1 = wt[o * 576 + (ci0 + 1) * 9 + tap];
    g_Wf[i] = pack_bf2(v0, v1);
}

// ---------- main kernel: one CTA per (b, h-pair), 256 threads / 8 warps ----------
__global__ __launch_bounds__(256, 1)
void patchconv_mma(const float* __restrict__ x, const float* __restrict__ bias,
                   float* __restrict__ out) {
    extern __shared__ __align__(16) char smem[];
    unsigned* xw  = (unsigned*)(smem + SM_XB);  // [r(4)][ci2(32)][w(136)] bf16x2, w = xcol+1
    float* scs    = (float*)(smem + SM_CS);     // EXACT fp32 channel sums [r][w(136)]
    float* sps    = (float*)(smem + SM_PS);     // 3x3 patch sums [hl][w0]
    float* sbias  = (float*)(smem + SM_BIAS);
    const uint32_t sb  = smem_u32(smem);
    const uint32_t wb0 = sb + SM_MB;

    const int tid = threadIdx.x, lane = tid & 31, wid = tid >> 5;
    const int h0 = blockIdx.x * 2, bb = blockIdx.y;

    if (tid == 0) MB_INIT(wb0, 1);
    if (tid < 128) sbias[tid] = bias[tid];
    __syncthreads();
    if (tid == 0) {
        MB_EXPECT(wb0, WALL);
        #pragma unroll
        for (int t9 = 0; t9 < 9; t9++)
            BULK_G2S(sb + SM_W + t9 * 16384, (const void*)(g_Wf + t9 * 4096), 16384, wb0);
    }

    // ---- stage x: transpose to [r][ci2][w] bf16x2 + EXACT fp32 channel sums ----
    const float* xb = x + (size_t)bb * CIN * HW;
    for (int u = wid; u < 20; u += 8) {                 // 4 rows x 5 w-chunks
        int r = u / 5, wc = u - r * 5;
        int w = wc * 32 + lane;                         // w = xcol + 1
        if (w < XW) {
            int hr = h0 - 1 + r;
            int xcol = w - 1;
            bool ok = (w < 131) && ((unsigned)hr < 128u) && ((unsigned)xcol < 128u);
            const float* sp = xb + (size_t)hr * WD + xcol;
            float cs = 0.f;
            unsigned* dst = xw + (r * 32) * XW + w;
            #pragma unroll 8
            for (int c2 = 0; c2 < 32; c2++) {
                float v0 = 0.f, v1 = 0.f;
                if (ok) {
                    v0 = __ldg(sp + (size_t)(2 * c2) * HW);
                    v1 = __ldg(sp + (size_t)(2 * c2 + 1) * HW);
                }
                cs += v0 + v1;
                dst[c2 * XW] = pack_bf2(v0, v1);
            }
            scs[r * XW + w] = cs;
        }
    }
    __syncthreads();
    {   // patch sums: output (hl, w0) <- sum cs[(hl+kh)][w0+kw]
        int hl = tid >> 7, wo = tid & 127;
        float s = 0.f;
        #pragma unroll
        for (int kh = 0; kh < 3; kh++)
            #pragma unroll
            for (int kw = 0; kw < 3; kw++)
                s += scs[(hl + kh) * XW + wo + kw];
        sps[tid] = s;
    }
    __syncthreads();

    // ---- main loop: 3 kh x 12 k16-steps, warp tile 64M(w) x 64N(o), NO in-loop barriers ----
    const int warp_m = wid >> 1, warp_n = wid & 1;
    const int hl  = warp_m >> 1;
    const int wbq = (warp_m & 1) * 64;
    const int ob  = warp_n * 64;
    const int woffl = wbq + (lane >> 2);       // + kw added per step (w = xcol+1)
    const unsigned boff = (warp_n * 8) * 32;   // g-window offset in uint2 units

    float acc[4][8][4];
    #pragma unroll
    for (int mi = 0; mi < 4; mi++)
        #pragma unroll
        for (int ni = 0; ni < 8; ni++)
            #pragma unroll
            for (int j = 0; j < 4; j++) acc[mi][ni][j] = 0.f;

    unsigned a[2][4][4];
    unsigned b[2][8][2];

    // single wait: all 9 weight tiles resident; load step-0 frags into slot 0
    MB_WAIT(wb0, 0);
    LOAD_B2(0, 0, 0);
    LOAD_A(0, hl * 32, woffl, 0);

    #pragma unroll 1
    for (int kh = 0; kh < 3; kh++) {
        const int rowci2 = (hl + kh) * 32;
        #pragma unroll
        for (int s12 = 0; s12 < 12; s12++) {
            const int cur = s12 & 1, nxt = cur ^ 1;
            if (s12 < 11) {
                const int ns = s12 + 1, nkw = ns >> 2, nss = ns & 3;
                LOAD_B2(nxt, kh * 3 + nkw, nss);
                LOAD_A(nxt, rowci2, woffl + nkw, nss);
            } else if (kh < 2) {
                LOAD_B2(nxt, (kh + 1) * 3, 0);
                LOAD_A(nxt, rowci2 + 32, woffl, 0);
            }
            #pragma unroll
            for (int mi = 0; mi < 4; mi++)
                #pragma unroll
                for (int ni = 0; ni < 8; ni++)
                    MMA16(acc[mi][ni], a[cur][mi], b[cur][ni]);
        }
    }

    // ---- epilogue: + bias[o] + 0.1*(h+w)*patch_sum (EXACT), 32B-sector stores ----
    const int hg = h0 + hl;
    float* outb = out + (size_t)bb * OC * HW + (size_t)hg * WD;
    #pragma unroll
    for (int mi = 0; mi < 4; mi++) {
        int w0 = wbq + mi * 16 + (lane >> 2);
        float c0 = 0.1f * (float)(hg + w0) * sps[hl * 128 + w0];
        float c1 = 0.1f * (float)(hg + w0 + 8) * sps[hl * 128 + w0 + 8];
        #pragma unroll
        for (int ni = 0; ni < 8; ni++) {
            int o = ob + ni * 8 + 2 * (lane & 3);
            float bz0 = sbias[o], bz1 = sbias[o + 1];
            float* p0 = outb + (size_t)o * HW;
            float* p1 = p0 + HW;
            p0[w0]     = acc[mi][ni][0] + c0 + bz0;
            p1[w0]     = acc[mi][ni][1] + c0 + bz1;
            p0[w0 + 8] = acc[mi][ni][2] + c1 + bz0;
            p1[w0 + 8] = acc[mi][ni][3] + c1 + bz1;
        }
    }
}

extern "C" void kernel_launch(void* const* d_in, const int* in_sizes, int n_in,
                              void* d_out, int out_size) {
    const float* x    = (const float*)d_in[0];
    const float* wt   = (const float*)d_in[1];
    const float* bias = (const float*)d_in[2];
    float* out        = (float*)d_out;
    cudaFuncSetAttribute(patchconv_mma, cudaFuncAttributeMaxDynamicSharedMemorySize, SM_TOT);
    prep_w<<<(9 * 4 * 16 * 32 * 2 + 255) / 256, 256>>>(wt);
    patchconv_mma<<<dim3(64, 16), 256, SM_TOT>>>(x, bias, out);
}